// round 5
// baseline (speedup 1.0000x reference)
#include <cuda_runtime.h>
#include <cuda_bf16.h>
#include <math_constants.h>
#include <mma.h>
#include <cstdint>

using namespace nvcuda;

// ---------------- output packing ----------------
#define LEN_RECON (512*4096)
#define LEN_DIST  (512*64*1024)
#define LEN_IDX   (512*64)
#define LEN_MU    (512*256)
#define LEN_LV    (512*256)
#define LEN_DMU   (512*768)
#define LEN_DLV   (512*768)

#define OFF_RECON 0
#define OFF_DIST  (OFF_RECON + LEN_RECON)
#define OFF_IDX   (OFF_DIST  + LEN_DIST)
#define OFF_MU    (OFF_IDX   + LEN_IDX)
#define OFF_LV    (OFF_MU    + LEN_MU)
#define OFF_DMU   (OFF_LV    + LEN_LV)
#define OFF_DLV   (OFF_DMU   + LEN_DMU)
#define OFF_PLV   (OFF_DLV   + LEN_DLV)

// ---------------- scratch ----------------
__device__ unsigned int g_hmaxu[512 * 512];
__device__ float g_hmax[512 * 512];
__device__ float g_h2[512 * 2048];
__device__ float g_h3[512 * 512];
__device__ float g_t[512 * 2048];
__device__ float g_p[512 * 1536];
__device__ float g_cat[512 * 2304];
__device__ float g_z2[512 * 768];
__device__ float g_xr2[512 * 64];
__device__ float g_book2[64 * 1024];
__device__ unsigned long long g_keys[512 * 64];

__device__ __forceinline__ unsigned int f32_ordered(float f)
{
    unsigned int b = __float_as_uint(f);
    return (b & 0x80000000u) ? ~b : (b | 0x80000000u);
}
__device__ __forceinline__ float f32_unordered(unsigned int u)
{
    return __uint_as_float((u & 0x80000000u) ? (u & 0x7FFFFFFFu) : ~u);
}

// ================ shared GEMM building blocks ================
// BM=128, BN=64, BK=32, 128 threads (4 warps), warp tile 64x32 (2x2 warps).
#define BMt 128
#define BNt 64
#define BKt 32
#define PADt 40

#define LOAD_REGS(k0)                                                          \
    {                                                                          \
        _Pragma("unroll")                                                      \
        for (int i = 0; i < 8; i++)                                            \
            ar[i] = *reinterpret_cast<const float4*>(                          \
                &Ap[(size_t)(bm + arow + i * 16) * lda + (k0) + ak4 * 4]);     \
        _Pragma("unroll")                                                      \
        for (int i = 0; i < 4; i++)                                            \
            br[i] = *reinterpret_cast<const float4*>(                          \
                &Wp[(size_t)(bn + arow + i * 16) * ldw + (k0) + ak4 * 4]);     \
    }

#define CVT_ST(hiP, loP, r, v)                                                 \
    {                                                                          \
        __nv_bfloat16 hx = __float2bfloat16((v).x);                            \
        __nv_bfloat16 hy = __float2bfloat16((v).y);                            \
        __nv_bfloat16 hz = __float2bfloat16((v).z);                            \
        __nv_bfloat16 hw = __float2bfloat16((v).w);                            \
        __nv_bfloat16* ph = (hiP) + (r) * PADt + ak4 * 4;                      \
        *reinterpret_cast<__nv_bfloat162*>(ph)     = __halves2bfloat162(hx, hy); \
        *reinterpret_cast<__nv_bfloat162*>(ph + 2) = __halves2bfloat162(hz, hw); \
        __nv_bfloat16* pl = (loP) + (r) * PADt + ak4 * 4;                      \
        *reinterpret_cast<__nv_bfloat162*>(pl) = __halves2bfloat162(           \
            __float2bfloat16((v).x - __bfloat162float(hx)),                    \
            __float2bfloat16((v).y - __bfloat162float(hy)));                   \
        *reinterpret_cast<__nv_bfloat162*>(pl + 2) = __halves2bfloat162(       \
            __float2bfloat16((v).z - __bfloat162float(hz)),                    \
            __float2bfloat16((v).w - __bfloat162float(hw)));                   \
    }

#define STAGE()                                                                \
    {                                                                          \
        _Pragma("unroll")                                                      \
        for (int i = 0; i < 8; i++) CVT_ST(Ahi, Alo, arow + i * 16, ar[i]);    \
        _Pragma("unroll")                                                      \
        for (int i = 0; i < 4; i++) CVT_ST(Bhi, Blo, arow + i * 16, br[i]);    \
    }

#define MAINLOOP()                                                             \
    LOAD_REGS(0);                                                              \
    STAGE();                                                                   \
    __syncthreads();                                                           \
    for (int t = 0; t < nt; t++) {                                             \
        if (t + 1 < nt) LOAD_REGS((t + 1) * BKt);                              \
        _Pragma("unroll")                                                      \
        for (int kk = 0; kk < BKt; kk += 16) {                                 \
            wmma::fragment<wmma::matrix_a, 16, 16, 16, __nv_bfloat16, wmma::row_major> ah[4], al[4]; \
            _Pragma("unroll")                                                  \
            for (int i = 0; i < 4; i++) {                                      \
                const __nv_bfloat16* pa = Ahi + (wm * 64 + i * 16) * PADt + kk; \
                wmma::load_matrix_sync(ah[i], pa, PADt);                       \
                wmma::load_matrix_sync(al[i], pa + BMt * PADt, PADt);          \
            }                                                                  \
            _Pragma("unroll")                                                  \
            for (int j = 0; j < 2; j++) {                                      \
                wmma::fragment<wmma::matrix_b, 16, 16, 16, __nv_bfloat16, wmma::col_major> bh, bl; \
                const __nv_bfloat16* pb = Bhi + (wn * 32 + j * 16) * PADt + kk; \
                wmma::load_matrix_sync(bh, pb, PADt);                          \
                wmma::load_matrix_sync(bl, pb + BNt * PADt, PADt);             \
                _Pragma("unroll")                                              \
                for (int i = 0; i < 4; i++) {                                  \
                    wmma::mma_sync(acc[i][j], ah[i], bh, acc[i][j]);           \
                    wmma::mma_sync(acc[i][j], ah[i], bl, acc[i][j]);           \
                    wmma::mma_sync(acc[i][j], al[i], bh, acc[i][j]);           \
                }                                                              \
            }                                                                  \
        }                                                                      \
        __syncthreads();                                                       \
        if (t + 1 < nt) { STAGE(); __syncthreads(); }                          \
    }

#define PATCH_STORE()                                                          \
    {                                                                          \
        _Pragma("unroll")                                                      \
        for (int i = 0; i < 4; i++)                                            \
            _Pragma("unroll")                                                  \
            for (int j = 0; j < 2; j++)                                        \
                wmma::store_matrix_sync(patch + (i * 16) * 36 + j * 16,        \
                                        acc[i][j], 36, wmma::mem_row_major);   \
        __syncwarp();                                                          \
    }

// ================= main GEMM =================
// modes: 0=C ; 1=maxpool into mp ; 2=C+mu/lv ; 3=C+plv ; 4=dmu/dlv/z2 (no C)
__global__ __launch_bounds__(128) void k_wgemm(
    const float* __restrict__ Ap, int lda,
    const float* __restrict__ Wp, int K,
    const float* __restrict__ bias,
    float* __restrict__ C, int N, int act, int mode,
    unsigned int* __restrict__ mp,
    float* __restrict__ aux0, float* __restrict__ aux1,
    const float* __restrict__ paux, float* __restrict__ z2out)
{
    const int ldw = K;
    extern __shared__ char smem[];
    __nv_bfloat16* Ahi = reinterpret_cast<__nv_bfloat16*>(smem);
    __nv_bfloat16* Alo = Ahi + BMt * PADt;
    __nv_bfloat16* Bhi = Alo + BMt * PADt;
    __nv_bfloat16* Blo = Bhi + BNt * PADt;

    const int tid = threadIdx.x, wid = tid >> 5, lid = tid & 31;
    const int bm = blockIdx.y * BMt, bn = blockIdx.x * BNt;
    const int wm = wid & 1, wn = wid >> 1;
    const int arow = tid >> 3, ak4 = tid & 7;

    float4 ar[8], br[4];
    wmma::fragment<wmma::accumulator, 16, 16, 16, float> acc[4][2];
#pragma unroll
    for (int i = 0; i < 4; i++)
#pragma unroll
        for (int j = 0; j < 2; j++)
            wmma::fill_fragment(acc[i][j], 0.0f);

    const int nt = K / BKt;
    MAINLOOP();

    float* patch = reinterpret_cast<float*>(smem) + wid * 64 * 36;
    PATCH_STORE();

    const int nb = bn + wn * 32;

    if (mode == 1) {
        const int bgrp = (bm + wm * 64) >> 6;
#pragma unroll
        for (int cg = 0; cg < 8; cg++) {
            float b4[4];
#pragma unroll
            for (int j = 0; j < 4; j++) b4[j] = __ldg(&bias[nb + cg * 4 + j]);
            float mx[4];
#pragma unroll
            for (int j = 0; j < 4; j++) {
                float v0 = patch[lid * 36 + cg * 4 + j] + b4[j];
                float v1 = patch[(lid + 32) * 36 + cg * 4 + j] + b4[j];
                v0 = v0 > 0.f ? v0 : 0.2f * v0;
                v1 = v1 > 0.f ? v1 : 0.2f * v1;
                mx[j] = fmaxf(v0, v1);
            }
#pragma unroll
            for (int off = 16; off; off >>= 1)
#pragma unroll
                for (int j = 0; j < 4; j++)
                    mx[j] = fmaxf(mx[j], __shfl_xor_sync(0xffffffffu, mx[j], off));
            if (lid == 0)
#pragma unroll
                for (int j = 0; j < 4; j++)
                    atomicMax(&mp[bgrp * N + nb + cg * 4 + j], f32_ordered(mx[j]));
        }
        return;
    }

#pragma unroll 2
    for (int rr = 0; rr < 2; rr++) {
        const int r = lid + rr * 32;
        const int m = bm + wm * 64 + r;
#pragma unroll
        for (int cg = 0; cg < 8; cg++) {
            const int n = nb + cg * 4;
            float4 v;
            float* vp = reinterpret_cast<float*>(&v);
#pragma unroll
            for (int j = 0; j < 4; j++) {
                float val = patch[r * 36 + cg * 4 + j] + __ldg(&bias[n + j]);
                if (act) val = val > 0.f ? val : 0.2f * val;
                vp[j] = val;
            }
            if (mode != 4)
                *reinterpret_cast<float4*>(&C[(size_t)m * N + n]) = v;
            if (mode == 2) {
                if (n < 256)
                    *reinterpret_cast<float4*>(&aux0[m * 256 + n]) = v;
                else
                    *reinterpret_cast<float4*>(&aux1[m * 256 + n - 256]) = v;
            } else if (mode == 3) {
                if (n >= 768)
                    *reinterpret_cast<float4*>(&aux0[m * 768 + n - 768]) = v;
            } else if (mode == 4) {
                if (n < 768) {
                    *reinterpret_cast<float4*>(&aux0[m * 768 + n]) = v;
                    float4 pv = *reinterpret_cast<const float4*>(&paux[(size_t)m * 1536 + n]);
                    float4 z;
                    z.x = v.x + pv.x; z.y = v.y + pv.y;
                    z.z = v.z + pv.z; z.w = v.w + pv.w;
                    *reinterpret_cast<float4*>(&z2out[m * 768 + n]) = z;
                } else {
                    *reinterpret_cast<float4*>(&aux1[m * 768 + n - 768]) = v;
                }
            }
        }
    }
}

// ================= tensorized dist + argmin =================
// grid (1024/64, 512/128, 64), block 128
__global__ __launch_bounds__(128) void k_distw(
    const float* __restrict__ recon,
    const float* __restrict__ book,
    const float* __restrict__ xr2,
    const float* __restrict__ book2,
    float* __restrict__ dist,
    unsigned long long* __restrict__ keys)
{
    extern __shared__ char smem[];
    __nv_bfloat16* Ahi = reinterpret_cast<__nv_bfloat16*>(smem);
    __nv_bfloat16* Alo = Ahi + BMt * PADt;
    __nv_bfloat16* Bhi = Alo + BMt * PADt;
    __nv_bfloat16* Blo = Bhi + BNt * PADt;

    const int tid = threadIdx.x, wid = tid >> 5, lid = tid & 31;
    const int c = blockIdx.z;
    const int bm = blockIdx.y * BMt, bn = blockIdx.x * BNt;
    const int wm = wid & 1, wn = wid >> 1;
    const int arow = tid >> 3, ak4 = tid & 7;

    const float* Ap = recon + c * 64;           // lda 4096
    const float* Wp = book + (size_t)c * 65536; // ldw 64
    const int lda = 4096, ldw = 64;

    float4 ar[8], br[4];
    wmma::fragment<wmma::accumulator, 16, 16, 16, float> acc[4][2];
#pragma unroll
    for (int i = 0; i < 4; i++)
#pragma unroll
        for (int j = 0; j < 2; j++)
            wmma::fill_fragment(acc[i][j], 0.0f);

    const int nt = 2;   // K = 64
    MAINLOOP();

    float* patch = reinterpret_cast<float*>(smem) + wid * 64 * 36;
    PATCH_STORE();

    const int snb = bn + wn * 32;
#pragma unroll 2
    for (int rr = 0; rr < 2; rr++) {
        const int r = lid + rr * 32;
        const int m = bm + wm * 64 + r;
        const float x2 = __ldg(&xr2[m * 64 + c]);
        unsigned long long kbest = ~0ull;
        float* drow = dist + ((size_t)m * 64 + c) * 1024;
#pragma unroll
        for (int cg = 0; cg < 8; cg++) {
            const int s = snb + cg * 4;
            float4 v;
            float* vp = reinterpret_cast<float*>(&v);
#pragma unroll
            for (int j = 0; j < 4; j++) {
                float dval = x2 + __ldg(&book2[c * 1024 + s + j])
                           - 2.0f * patch[r * 36 + cg * 4 + j];
                vp[j] = dval;
                unsigned long long key =
                    ((unsigned long long)f32_ordered(dval) << 32) | (unsigned int)(s + j);
                kbest = min(kbest, key);
            }
            *reinterpret_cast<float4*>(&drow[s]) = v;
        }
        atomicMin(&keys[m * 64 + c], kbest);
    }
}

// ================= elementwise helpers =================
__global__ void k_inithmax(unsigned int* __restrict__ hmaxu)
{
    int idx = blockIdx.x * blockDim.x + threadIdx.x;
    if (idx < 512 * 512) hmaxu[idx] = f32_ordered(-CUDART_INF_F);
}

__global__ void k_cvthmax(const unsigned int* __restrict__ hmaxu, float* __restrict__ hmax)
{
    int idx = blockIdx.x * blockDim.x + threadIdx.x;
    if (idx < 512 * 512) hmax[idx] = f32_unordered(hmaxu[idx]);
}

__global__ void k_cat(const float* __restrict__ z1, const float* __restrict__ h,
                      float* __restrict__ dst)
{
    int idx = blockIdx.x * blockDim.x + threadIdx.x;
    if (idx >= 512 * 2304) return;
    int b = idx / 2304, j = idx - b * 2304;
    dst[idx] = (j < 256) ? z1[(size_t)b * 512 + j] : h[(size_t)b * 2048 + (j - 256)];
}

__global__ void k_initkeys(unsigned long long* __restrict__ keys)
{
    int idx = blockIdx.x * blockDim.x + threadIdx.x;
    if (idx < 512 * 64) keys[idx] = ~0ull;
}

__global__ void k_rowsq(const float* __restrict__ src, float* __restrict__ dst, int nrows)
{
    int idx = blockIdx.x * blockDim.x + threadIdx.x;
    if (idx >= nrows) return;
    const float4* p = reinterpret_cast<const float4*>(src + (size_t)idx * 64);
    float s = 0.f;
#pragma unroll
    for (int i = 0; i < 16; i++) {
        float4 v = p[i];
        s += v.x * v.x + v.y * v.y + v.z * v.z + v.w * v.w;
    }
    dst[idx] = s;
}

__global__ void k_writeidx(const unsigned long long* __restrict__ keys,
                           float* __restrict__ out)
{
    int idx = blockIdx.x * blockDim.x + threadIdx.x;
    if (idx < 512 * 64)
        out[idx] = (float)(unsigned int)(keys[idx] & 0xFFFFFFFFull);
}

// ================= launcher =================
#define GEMM_SMEM 36864

extern "C" void kernel_launch(void* const* d_in, const int* in_sizes, int n_in,
                              void* d_out, int out_size)
{
    const float* x        = (const float*)d_in[0];
    const float* codebook = (const float*)d_in[1];
    const float* enc_w1   = (const float*)d_in[2];
    const float* enc_b1   = (const float*)d_in[3];
    const float* enc_w2   = (const float*)d_in[4];
    const float* enc_b2   = (const float*)d_in[5];
    const float* inf1_w   = (const float*)d_in[6];
    const float* inf1_b   = (const float*)d_in[7];
    const float* inf2_w1  = (const float*)d_in[8];
    const float* inf2_b1  = (const float*)d_in[9];
    const float* inf2_w2  = (const float*)d_in[10];
    const float* inf2_b2  = (const float*)d_in[11];
    const float* prior_w1 = (const float*)d_in[12];
    const float* prior_b1 = (const float*)d_in[13];
    const float* prior_w2 = (const float*)d_in[14];
    const float* prior_b2 = (const float*)d_in[15];
    const float* dec_w1   = (const float*)d_in[16];
    const float* dec_b1   = (const float*)d_in[17];
    const float* dec_w2   = (const float*)d_in[18];
    const float* dec_b2   = (const float*)d_in[19];
    float* out = (float*)d_out;

    float *hmax, *h2, *h3, *t, *p, *cat, *z2, *xr2, *book2;
    unsigned int* hmaxu;
    unsigned long long* keys;
    cudaGetSymbolAddress((void**)&hmaxu, g_hmaxu);
    cudaGetSymbolAddress((void**)&hmax,  g_hmax);
    cudaGetSymbolAddress((void**)&h2,    g_h2);
    cudaGetSymbolAddress((void**)&h3,    g_h3);
    cudaGetSymbolAddress((void**)&t,     g_t);
    cudaGetSymbolAddress((void**)&p,     g_p);
    cudaGetSymbolAddress((void**)&cat,   g_cat);
    cudaGetSymbolAddress((void**)&z2,    g_z2);
    cudaGetSymbolAddress((void**)&xr2,   g_xr2);
    cudaGetSymbolAddress((void**)&book2, g_book2);
    cudaGetSymbolAddress((void**)&keys,  g_keys);

    cudaFuncSetAttribute(k_wgemm, cudaFuncAttributeMaxDynamicSharedMemorySize, GEMM_SMEM);
    cudaFuncSetAttribute(k_distw, cudaFuncAttributeMaxDynamicSharedMemorySize, GEMM_SMEM);

    // 1) enc1 + fused maxpool
    k_inithmax<<<(512*512+255)/256, 256>>>(hmaxu);
    k_wgemm<<<dim3(512/64, 32768/128), 128, GEMM_SMEM>>>(
        x, 64, enc_w1, 64, enc_b1, nullptr, 512, 1, 1, hmaxu, nullptr, nullptr, nullptr, nullptr);
    k_cvthmax<<<(512*512+255)/256, 256>>>(hmaxu, hmax);
    // 2) enc2
    k_wgemm<<<dim3(2048/64, 4), 128, GEMM_SMEM>>>(
        hmax, 512, enc_w2, 512, enc_b2, h2, 2048, 0, 0, nullptr, nullptr, nullptr, nullptr, nullptr);
    // 3) inf1 (+ mu/lv)
    k_wgemm<<<dim3(512/64, 4), 128, GEMM_SMEM>>>(
        h2, 2048, inf1_w, 2048, inf1_b, h3, 512, 0, 2, nullptr,
        out + OFF_MU, out + OFF_LV, nullptr, nullptr);
    // 4) prior
    k_wgemm<<<dim3(2048/64, 4), 128, GEMM_SMEM>>>(
        h3, 512, prior_w1, 256, prior_b1, t, 2048, 1, 0, nullptr, nullptr, nullptr, nullptr, nullptr);
    k_wgemm<<<dim3(1536/64, 4), 128, GEMM_SMEM>>>(
        t, 2048, prior_w2, 2048, prior_b2, p, 1536, 0, 3, nullptr,
        out + OFF_PLV, nullptr, nullptr, nullptr);
    // 5) inf2
    k_cat<<<(512*2304+255)/256, 256>>>(h3, h2, cat);
    k_wgemm<<<dim3(2048/64, 4), 128, GEMM_SMEM>>>(
        cat, 2304, inf2_w1, 2304, inf2_b1, t, 2048, 1, 0, nullptr, nullptr, nullptr, nullptr, nullptr);
    k_wgemm<<<dim3(1536/64, 4), 128, GEMM_SMEM>>>(
        t, 2048, inf2_w2, 2048, inf2_b2, nullptr, 1536, 0, 4, nullptr,
        out + OFF_DMU, out + OFF_DLV, p, z2);
    // 6) decoder
    k_wgemm<<<dim3(2048/64, 4), 128, GEMM_SMEM>>>(
        z2, 768, dec_w1, 768, dec_b1, t, 2048, 1, 0, nullptr, nullptr, nullptr, nullptr, nullptr);
    k_wgemm<<<dim3(4096/64, 4), 128, GEMM_SMEM>>>(
        t, 2048, dec_w2, 2048, dec_b2, out + OFF_RECON, 4096, 0, 0, nullptr, nullptr, nullptr, nullptr, nullptr);
    // 7) dist + argmin (tensorized)
    k_rowsq<<<(512*64+255)/256, 256>>>(out + OFF_RECON, xr2, 512*64);
    k_rowsq<<<(64*1024+255)/256, 256>>>(codebook, book2, 64*1024);
    k_initkeys<<<(512*64+255)/256, 256>>>(keys);
    k_distw<<<dim3(1024/64, 512/128, 64), 128, GEMM_SMEM>>>(
        out + OFF_RECON, codebook, xr2, book2, out + OFF_DIST, keys);
    k_writeidx<<<(512*64+255)/256, 256>>>(keys, out + OFF_IDX);
}

// round 8
// speedup vs baseline: 1.9051x; 1.9051x over previous
#include <cuda_runtime.h>
#include <cuda_bf16.h>
#include <math_constants.h>
#include <mma.h>
#include <cstdint>

using namespace nvcuda;

// ---------------- output packing ----------------
#define LEN_RECON (512*4096)
#define LEN_DIST  (512*64*1024)
#define LEN_IDX   (512*64)
#define LEN_MU    (512*256)
#define LEN_LV    (512*256)
#define LEN_DMU   (512*768)
#define LEN_DLV   (512*768)

#define OFF_RECON 0
#define OFF_DIST  (OFF_RECON + LEN_RECON)
#define OFF_IDX   (OFF_DIST  + LEN_DIST)
#define OFF_MU    (OFF_IDX   + LEN_IDX)
#define OFF_LV    (OFF_MU    + LEN_MU)
#define OFF_DMU   (OFF_LV    + LEN_LV)
#define OFF_DLV   (OFF_DMU   + LEN_DMU)
#define OFF_PLV   (OFF_DLV   + LEN_DLV)

// ---------------- scratch ----------------
__device__ unsigned int g_hmaxu[512 * 512];
__device__ float g_hmax[512 * 512];
__device__ float g_h2[512 * 2048];
__device__ float g_h3[512 * 512];
__device__ float g_t[512 * 2048];
__device__ float g_p[512 * 1536];
__device__ float g_cat[512 * 2304];
__device__ float g_z2[512 * 768];
__device__ float g_xr2[512 * 64];
__device__ float g_book2[64 * 1024];
__device__ unsigned long long g_keys[512 * 64];

__device__ __forceinline__ unsigned int f32_ordered(float f)
{
    unsigned int b = __float_as_uint(f);
    return (b & 0x80000000u) ? ~b : (b | 0x80000000u);
}
__device__ __forceinline__ float f32_unordered(unsigned int u)
{
    return __uint_as_float((u & 0x80000000u) ? (u & 0x7FFFFFFFu) : ~u);
}

// ================ R4 GEMM building blocks (256 thr, 8 warps, 32x32 warp tile) ====
#define BMt 128
#define BNt 64
#define BKt 32
#define PADt 40

#define LOAD_REGS(k0)                                                          \
    {                                                                          \
        _Pragma("unroll")                                                      \
        for (int i = 0; i < 4; i++)                                            \
            ar[i] = *reinterpret_cast<const float4*>(                          \
                &Ap[(size_t)(bm + arow + i * 32) * lda + (k0) + ak4 * 4]);     \
        _Pragma("unroll")                                                      \
        for (int i = 0; i < 2; i++)                                            \
            br[i] = *reinterpret_cast<const float4*>(                          \
                &Wp[(size_t)(bn + arow + i * 32) * ldw + (k0) + ak4 * 4]);     \
    }

#define CVT_ST(hiP, loP, r, v)                                                 \
    {                                                                          \
        __nv_bfloat16 hx = __float2bfloat16((v).x);                            \
        __nv_bfloat16 hy = __float2bfloat16((v).y);                            \
        __nv_bfloat16 hz = __float2bfloat16((v).z);                            \
        __nv_bfloat16 hw = __float2bfloat16((v).w);                            \
        __nv_bfloat16* ph = (hiP) + (r) * PADt + ak4 * 4;                      \
        *reinterpret_cast<__nv_bfloat162*>(ph)     = __halves2bfloat162(hx, hy); \
        *reinterpret_cast<__nv_bfloat162*>(ph + 2) = __halves2bfloat162(hz, hw); \
        __nv_bfloat16* pl = (loP) + (r) * PADt + ak4 * 4;                      \
        *reinterpret_cast<__nv_bfloat162*>(pl) = __halves2bfloat162(           \
            __float2bfloat16((v).x - __bfloat162float(hx)),                    \
            __float2bfloat16((v).y - __bfloat162float(hy)));                   \
        *reinterpret_cast<__nv_bfloat162*>(pl + 2) = __halves2bfloat162(       \
            __float2bfloat16((v).z - __bfloat162float(hz)),                    \
            __float2bfloat16((v).w - __bfloat162float(hw)));                   \
    }

#define STAGE()                                                                \
    {                                                                          \
        _Pragma("unroll")                                                      \
        for (int i = 0; i < 4; i++) CVT_ST(Ahi, Alo, arow + i * 32, ar[i]);    \
        _Pragma("unroll")                                                      \
        for (int i = 0; i < 2; i++) CVT_ST(Bhi, Blo, arow + i * 32, br[i]);    \
    }

#define MAINLOOP()                                                             \
    LOAD_REGS(0);                                                              \
    STAGE();                                                                   \
    __syncthreads();                                                           \
    for (int t = 0; t < nt; t++) {                                             \
        if (t + 1 < nt) LOAD_REGS((t + 1) * BKt);                              \
        _Pragma("unroll")                                                      \
        for (int kk = 0; kk < BKt; kk += 16) {                                 \
            wmma::fragment<wmma::matrix_a, 16, 16, 16, __nv_bfloat16, wmma::row_major> ah[2], al[2]; \
            wmma::fragment<wmma::matrix_b, 16, 16, 16, __nv_bfloat16, wmma::col_major> bh[2], bl[2]; \
            _Pragma("unroll")                                                  \
            for (int i = 0; i < 2; i++) {                                      \
                const __nv_bfloat16* pa = Ahi + (wm * 32 + i * 16) * PADt + kk; \
                wmma::load_matrix_sync(ah[i], pa, PADt);                       \
                wmma::load_matrix_sync(al[i], pa + BMt * PADt, PADt);          \
            }                                                                  \
            _Pragma("unroll")                                                  \
            for (int j = 0; j < 2; j++) {                                      \
                const __nv_bfloat16* pb = Bhi + (wn * 32 + j * 16) * PADt + kk; \
                wmma::load_matrix_sync(bh[j], pb, PADt);                       \
                wmma::load_matrix_sync(bl[j], pb + BNt * PADt, PADt);          \
            }                                                                  \
            _Pragma("unroll")                                                  \
            for (int i = 0; i < 2; i++)                                        \
                _Pragma("unroll")                                              \
                for (int j = 0; j < 2; j++) {                                  \
                    wmma::mma_sync(acc[i][j], ah[i], bh[j], acc[i][j]);        \
                    wmma::mma_sync(acc[i][j], ah[i], bl[j], acc[i][j]);        \
                    wmma::mma_sync(acc[i][j], al[i], bh[j], acc[i][j]);        \
                }                                                              \
        }                                                                      \
        __syncthreads();                                                       \
        if (t + 1 < nt) { STAGE(); __syncthreads(); }                          \
    }

#define PATCH_STORE()                                                          \
    {                                                                          \
        _Pragma("unroll")                                                      \
        for (int i = 0; i < 2; i++)                                            \
            _Pragma("unroll")                                                  \
            for (int j = 0; j < 2; j++)                                        \
                wmma::store_matrix_sync(patch + i * 16 * 32 + j * 16,          \
                                        acc[i][j], 32, wmma::mem_row_major);   \
        __syncwarp();                                                          \
    }

// ================= main GEMM =================
// modes: 0=C ; 1=maxpool into mp ; 2=C+mu/lv ; 3=C+plv ; 4=dmu/dlv/z2 (no C)
__global__ __launch_bounds__(256) void k_wgemm(
    const float* __restrict__ Ap, int lda,
    const float* __restrict__ Wp, int K,
    const float* __restrict__ bias,
    float* __restrict__ C, int N, int act, int mode,
    unsigned int* __restrict__ mp,
    float* __restrict__ aux0, float* __restrict__ aux1,
    const float* __restrict__ paux, float* __restrict__ z2out)
{
    const int ldw = K;
    extern __shared__ char smem[];
    __nv_bfloat16* Ahi = reinterpret_cast<__nv_bfloat16*>(smem);
    __nv_bfloat16* Alo = Ahi + BMt * PADt;
    __nv_bfloat16* Bhi = Alo + BMt * PADt;
    __nv_bfloat16* Blo = Bhi + BNt * PADt;

    const int tid = threadIdx.x, wid = tid >> 5, lid = tid & 31;
    const int bm = blockIdx.y * BMt, bn = blockIdx.x * BNt;
    const int wm = wid & 3, wn = wid >> 2;     // 4 x 2 warps, 32x32 each
    const int arow = tid >> 3, ak4 = tid & 7;

    float4 ar[4], br[2];
    wmma::fragment<wmma::accumulator, 16, 16, 16, float> acc[2][2];
#pragma unroll
    for (int i = 0; i < 2; i++)
#pragma unroll
        for (int j = 0; j < 2; j++)
            wmma::fill_fragment(acc[i][j], 0.0f);

    const int nt = K / BKt;
    MAINLOOP();

    float* patch = reinterpret_cast<float*>(smem) + wid * 1024;
    PATCH_STORE();

    const int cbase = bn + wn * 32;
    const int c0 = (lid & 7) * 4;

    if (mode == 1) {
        float mx[4] = {-CUDART_INF_F, -CUDART_INF_F, -CUDART_INF_F, -CUDART_INF_F};
#pragma unroll
        for (int it = 0; it < 8; it++) {
            int r = it * 4 + (lid >> 3);
#pragma unroll
            for (int j = 0; j < 4; j++) {
                float rr = patch[r * 32 + c0 + j] + __ldg(&bias[cbase + c0 + j]);
                rr = rr > 0.f ? rr : 0.2f * rr;
                mx[j] = fmaxf(mx[j], rr);
            }
        }
        int b = (bm + wm * 32) >> 6;
#pragma unroll
        for (int j = 0; j < 4; j++)
            atomicMax(&mp[b * N + cbase + c0 + j], f32_ordered(mx[j]));
        return;
    }

#pragma unroll
    for (int it = 0; it < 8; it++) {
        int r = it * 4 + (lid >> 3);
        int m = bm + wm * 32 + r;
        int n = cbase + c0;
        float4 v;
        float* vp = reinterpret_cast<float*>(&v);
#pragma unroll
        for (int j = 0; j < 4; j++) {
            float rr = patch[r * 32 + c0 + j] + __ldg(&bias[n + j]);
            if (act) rr = rr > 0.f ? rr : 0.2f * rr;
            vp[j] = rr;
        }
        if (mode != 4)
            *reinterpret_cast<float4*>(&C[(size_t)m * N + n]) = v;
        if (mode == 2) {
            if (n < 256)
                *reinterpret_cast<float4*>(&aux0[m * 256 + n]) = v;
            else
                *reinterpret_cast<float4*>(&aux1[m * 256 + n - 256]) = v;
        } else if (mode == 3) {
            if (n >= 768)
                *reinterpret_cast<float4*>(&aux0[m * 768 + n - 768]) = v;
        } else if (mode == 4) {
            if (n < 768) {
                *reinterpret_cast<float4*>(&aux0[m * 768 + n]) = v;
                float4 pv = *reinterpret_cast<const float4*>(&paux[(size_t)m * 1536 + n]);
                float4 z;
                z.x = v.x + pv.x; z.y = v.y + pv.y;
                z.z = v.z + pv.z; z.w = v.w + pv.w;
                *reinterpret_cast<float4*>(&z2out[m * 768 + n]) = z;
            } else {
                *reinterpret_cast<float4*>(&aux1[m * 768 + n - 768]) = v;
            }
        }
    }
}

// ================= tensorized dist + argmin (same 8-warp config) =================
// grid (1024/64, 512/128, 64), block 256
__global__ __launch_bounds__(256) void k_distw(
    const float* __restrict__ recon,
    const float* __restrict__ book,
    const float* __restrict__ xr2,
    const float* __restrict__ book2,
    float* __restrict__ dist,
    unsigned long long* __restrict__ keys)
{
    extern __shared__ char smem[];
    __nv_bfloat16* Ahi = reinterpret_cast<__nv_bfloat16*>(smem);
    __nv_bfloat16* Alo = Ahi + BMt * PADt;
    __nv_bfloat16* Bhi = Alo + BMt * PADt;
    __nv_bfloat16* Blo = Bhi + BNt * PADt;

    const int tid = threadIdx.x, wid = tid >> 5, lid = tid & 31;
    const int c = blockIdx.z;
    const int bm = blockIdx.y * BMt, bn = blockIdx.x * BNt;
    const int wm = wid & 3, wn = wid >> 2;
    const int arow = tid >> 3, ak4 = tid & 7;

    const float* Ap = recon + c * 64;            // lda 4096
    const float* Wp = book + (size_t)c * 65536;  // ldw 64
    const int lda = 4096, ldw = 64;

    float4 ar[4], br[2];
    wmma::fragment<wmma::accumulator, 16, 16, 16, float> acc[2][2];
#pragma unroll
    for (int i = 0; i < 2; i++)
#pragma unroll
        for (int j = 0; j < 2; j++)
            wmma::fill_fragment(acc[i][j], 0.0f);

    const int nt = 2;    // K = 64
    MAINLOOP();

    float* patch = reinterpret_cast<float*>(smem) + wid * 1024;
    PATCH_STORE();

    const int sbase = bn + wn * 32;
    const int c0 = (lid & 7) * 4;

#pragma unroll
    for (int it = 0; it < 8; it++) {
        int r = it * 4 + (lid >> 3);
        int m = bm + wm * 32 + r;
        int s = sbase + c0;
        float x2 = __ldg(&xr2[m * 64 + c]);
        float4 v;
        float* vp = reinterpret_cast<float*>(&v);
        unsigned long long kbest = ~0ull;
#pragma unroll
        for (int j = 0; j < 4; j++) {
            float dval = x2 + __ldg(&book2[c * 1024 + s + j])
                       - 2.0f * patch[r * 32 + c0 + j];
            vp[j] = dval;
            unsigned long long key =
                ((unsigned long long)f32_ordered(dval) << 32) | (unsigned int)(s + j);
            kbest = min(kbest, key);
        }
        *reinterpret_cast<float4*>(&dist[((size_t)m * 64 + c) * 1024 + s]) = v;
        // reduce over the 8 lanes sharing this row (contiguous lanes, width 8)
#pragma unroll
        for (int off = 4; off; off >>= 1) {
            unsigned long long o = __shfl_xor_sync(0xffffffffu, kbest, off, 8);
            kbest = min(kbest, o);
        }
        if ((lid & 7) == 0) atomicMin(&keys[m * 64 + c], kbest);
    }
}

// ================= elementwise helpers =================
__global__ void k_inithmax(unsigned int* __restrict__ hmaxu)
{
    int idx = blockIdx.x * blockDim.x + threadIdx.x;
    if (idx < 512 * 512) hmaxu[idx] = f32_ordered(-CUDART_INF_F);
}

__global__ void k_cvthmax(const unsigned int* __restrict__ hmaxu, float* __restrict__ hmax)
{
    int idx = blockIdx.x * blockDim.x + threadIdx.x;
    if (idx < 512 * 512) hmax[idx] = f32_unordered(hmaxu[idx]);
}

__global__ void k_cat(const float* __restrict__ z1, const float* __restrict__ h,
                      float* __restrict__ dst)
{
    int idx = blockIdx.x * blockDim.x + threadIdx.x;
    if (idx >= 512 * 2304) return;
    int b = idx / 2304, j = idx - b * 2304;
    dst[idx] = (j < 256) ? z1[(size_t)b * 512 + j] : h[(size_t)b * 2048 + (j - 256)];
}

__global__ void k_initkeys(unsigned long long* __restrict__ keys)
{
    int idx = blockIdx.x * blockDim.x + threadIdx.x;
    if (idx < 512 * 64) keys[idx] = ~0ull;
}

__global__ void k_rowsq(const float* __restrict__ src, float* __restrict__ dst, int nrows)
{
    int idx = blockIdx.x * blockDim.x + threadIdx.x;
    if (idx >= nrows) return;
    const float4* p = reinterpret_cast<const float4*>(src + (size_t)idx * 64);
    float s = 0.f;
#pragma unroll
    for (int i = 0; i < 16; i++) {
        float4 v = p[i];
        s += v.x * v.x + v.y * v.y + v.z * v.z + v.w * v.w;
    }
    dst[idx] = s;
}

__global__ void k_writeidx(const unsigned long long* __restrict__ keys,
                           float* __restrict__ out)
{
    int idx = blockIdx.x * blockDim.x + threadIdx.x;
    if (idx < 512 * 64)
        out[idx] = (float)(unsigned int)(keys[idx] & 0xFFFFFFFFull);
}

// ================= launcher =================
#define GEMM_SMEM 32768

extern "C" void kernel_launch(void* const* d_in, const int* in_sizes, int n_in,
                              void* d_out, int out_size)
{
    const float* x        = (const float*)d_in[0];
    const float* codebook = (const float*)d_in[1];
    const float* enc_w1   = (const float*)d_in[2];
    const float* enc_b1   = (const float*)d_in[3];
    const float* enc_w2   = (const float*)d_in[4];
    const float* enc_b2   = (const float*)d_in[5];
    const float* inf1_w   = (const float*)d_in[6];
    const float* inf1_b   = (const float*)d_in[7];
    const float* inf2_w1  = (const float*)d_in[8];
    const float* inf2_b1  = (const float*)d_in[9];
    const float* inf2_w2  = (const float*)d_in[10];
    const float* inf2_b2  = (const float*)d_in[11];
    const float* prior_w1 = (const float*)d_in[12];
    const float* prior_b1 = (const float*)d_in[13];
    const float* prior_w2 = (const float*)d_in[14];
    const float* prior_b2 = (const float*)d_in[15];
    const float* dec_w1   = (const float*)d_in[16];
    const float* dec_b1   = (const float*)d_in[17];
    const float* dec_w2   = (const float*)d_in[18];
    const float* dec_b2   = (const float*)d_in[19];
    float* out = (float*)d_out;

    float *hmax, *h2, *h3, *t, *p, *cat, *z2, *xr2, *book2;
    unsigned int* hmaxu;
    unsigned long long* keys;
    cudaGetSymbolAddress((void**)&hmaxu, g_hmaxu);
    cudaGetSymbolAddress((void**)&hmax,  g_hmax);
    cudaGetSymbolAddress((void**)&h2,    g_h2);
    cudaGetSymbolAddress((void**)&h3,    g_h3);
    cudaGetSymbolAddress((void**)&t,     g_t);
    cudaGetSymbolAddress((void**)&p,     g_p);
    cudaGetSymbolAddress((void**)&cat,   g_cat);
    cudaGetSymbolAddress((void**)&z2,    g_z2);
    cudaGetSymbolAddress((void**)&xr2,   g_xr2);
    cudaGetSymbolAddress((void**)&book2, g_book2);
    cudaGetSymbolAddress((void**)&keys,  g_keys);

    cudaFuncSetAttribute(k_wgemm, cudaFuncAttributeMaxDynamicSharedMemorySize, GEMM_SMEM);
    cudaFuncSetAttribute(k_distw, cudaFuncAttributeMaxDynamicSharedMemorySize, GEMM_SMEM);

    // 1) enc1 + fused maxpool
    k_inithmax<<<(512*512+255)/256, 256>>>(hmaxu);
    k_wgemm<<<dim3(512/64, 32768/128), 256, GEMM_SMEM>>>(
        x, 64, enc_w1, 64, enc_b1, nullptr, 512, 1, 1, hmaxu, nullptr, nullptr, nullptr, nullptr);
    k_cvthmax<<<(512*512+255)/256, 256>>>(hmaxu, hmax);
    // 2) enc2
    k_wgemm<<<dim3(2048/64, 4), 256, GEMM_SMEM>>>(
        hmax, 512, enc_w2, 512, enc_b2, h2, 2048, 0, 0, nullptr, nullptr, nullptr, nullptr, nullptr);
    // 3) inf1 (+ mu/lv)
    k_wgemm<<<dim3(512/64, 4), 256, GEMM_SMEM>>>(
        h2, 2048, inf1_w, 2048, inf1_b, h3, 512, 0, 2, nullptr,
        out + OFF_MU, out + OFF_LV, nullptr, nullptr);
    // 4) prior
    k_wgemm<<<dim3(2048/64, 4), 256, GEMM_SMEM>>>(
        h3, 512, prior_w1, 256, prior_b1, t, 2048, 1, 0, nullptr, nullptr, nullptr, nullptr, nullptr);
    k_wgemm<<<dim3(1536/64, 4), 256, GEMM_SMEM>>>(
        t, 2048, prior_w2, 2048, prior_b2, p, 1536, 0, 3, nullptr,
        out + OFF_PLV, nullptr, nullptr, nullptr);
    // 5) inf2
    k_cat<<<(512*2304+255)/256, 256>>>(h3, h2, cat);
    k_wgemm<<<dim3(2048/64, 4), 256, GEMM_SMEM>>>(
        cat, 2304, inf2_w1, 2304, inf2_b1, t, 2048, 1, 0, nullptr, nullptr, nullptr, nullptr, nullptr);
    k_wgemm<<<dim3(1536/64, 4), 256, GEMM_SMEM>>>(
        t, 2048, inf2_w2, 2048, inf2_b2, nullptr, 1536, 0, 4, nullptr,
        out + OFF_DMU, out + OFF_DLV, p, z2);
    // 6) decoder
    k_wgemm<<<dim3(2048/64, 4), 256, GEMM_SMEM>>>(
        z2, 768, dec_w1, 768, dec_b1, t, 2048, 1, 0, nullptr, nullptr, nullptr, nullptr, nullptr);
    k_wgemm<<<dim3(4096/64, 4), 256, GEMM_SMEM>>>(
        t, 2048, dec_w2, 2048, dec_b2, out + OFF_RECON, 4096, 0, 0, nullptr, nullptr, nullptr, nullptr, nullptr);
    // 7) dist + argmin (tensorized)
    k_rowsq<<<(512*64+255)/256, 256>>>(out + OFF_RECON, xr2, 512*64);
    k_rowsq<<<(64*1024+255)/256, 256>>>(codebook, book2, 64*1024);
    k_initkeys<<<(512*64+255)/256, 256>>>(keys);
    k_distw<<<dim3(1024/64, 512/128, 64), 256, GEMM_SMEM>>>(
        out + OFF_RECON, codebook, xr2, book2, out + OFF_DIST, keys);
    k_writeidx<<<(512*64+255)/256, 256>>>(keys, out + OFF_IDX);
}

// round 10
// speedup vs baseline: 2.0273x; 1.0641x over previous
#include <cuda_runtime.h>
#include <cuda_bf16.h>
#include <math_constants.h>
#include <mma.h>
#include <cstdint>

using namespace nvcuda;

// ---------------- output packing ----------------
#define LEN_RECON (512*4096)
#define LEN_DIST  (512*64*1024)
#define LEN_IDX   (512*64)
#define LEN_MU    (512*256)
#define LEN_LV    (512*256)
#define LEN_DMU   (512*768)
#define LEN_DLV   (512*768)

#define OFF_RECON 0
#define OFF_DIST  (OFF_RECON + LEN_RECON)
#define OFF_IDX   (OFF_DIST  + LEN_DIST)
#define OFF_MU    (OFF_IDX   + LEN_IDX)
#define OFF_LV    (OFF_MU    + LEN_MU)
#define OFF_DMU   (OFF_LV    + LEN_LV)
#define OFF_DLV   (OFF_DMU   + LEN_DMU)
#define OFF_PLV   (OFF_DLV   + LEN_DLV)

// ---------------- scratch ----------------
__device__ unsigned int g_hmaxu[512 * 512];
__device__ float g_hmax[512 * 512];
__device__ float g_h2[512 * 2048];
__device__ float g_h3[512 * 512];
__device__ float g_t[512 * 2048];
__device__ float g_p[512 * 1536];
__device__ float g_cat[512 * 2304];
__device__ float g_z2[512 * 768];
__device__ float g_xr2[512 * 64];
__device__ float g_book2[64 * 1024];
__device__ unsigned long long g_keys[512 * 64];

__device__ __forceinline__ unsigned int f32_ordered(float f)
{
    unsigned int b = __float_as_uint(f);
    return (b & 0x80000000u) ? ~b : (b | 0x80000000u);
}
__device__ __forceinline__ float f32_unordered(unsigned int u)
{
    return __uint_as_float((u & 0x80000000u) ? (u & 0x7FFFFFFFu) : ~u);
}

// ================ GEMM building blocks (256 thr, 8 warps, 32x32 warp tile) ====
// double-buffered smem stages
#define BMt 128
#define BNt 64
#define BKt 32
#define PADt 40
#define STG_BYTES 30720   // per stage: (128+64)*40*2B*2(hi+lo)

#define AHI(s) (reinterpret_cast<__nv_bfloat16*>(smem + (s) * STG_BYTES))
#define ALO(s) (AHI(s) + BMt * PADt)
#define BHI(s) (ALO(s) + BMt * PADt)
#define BLO(s) (BHI(s) + BNt * PADt)

#define LOAD_REGS(k0)                                                          \
    {                                                                          \
        _Pragma("unroll")                                                      \
        for (int i = 0; i < 4; i++)                                            \
            ar[i] = *reinterpret_cast<const float4*>(                          \
                &Ap[(size_t)(bm + arow + i * 32) * lda + (k0) + ak4 * 4]);     \
        _Pragma("unroll")                                                      \
        for (int i = 0; i < 2; i++)                                            \
            br[i] = *reinterpret_cast<const float4*>(                          \
                &Wp[(size_t)(bn + arow + i * 32) * ldw + (k0) + ak4 * 4]);     \
    }

#define CVT_ST(hiP, loP, r, v)                                                 \
    {                                                                          \
        __nv_bfloat16 hx = __float2bfloat16((v).x);                            \
        __nv_bfloat16 hy = __float2bfloat16((v).y);                            \
        __nv_bfloat16 hz = __float2bfloat16((v).z);                            \
        __nv_bfloat16 hw = __float2bfloat16((v).w);                            \
        __nv_bfloat16* ph = (hiP) + (r) * PADt + ak4 * 4;                      \
        *reinterpret_cast<__nv_bfloat162*>(ph)     = __halves2bfloat162(hx, hy); \
        *reinterpret_cast<__nv_bfloat162*>(ph + 2) = __halves2bfloat162(hz, hw); \
        __nv_bfloat16* pl = (loP) + (r) * PADt + ak4 * 4;                      \
        *reinterpret_cast<__nv_bfloat162*>(pl) = __halves2bfloat162(           \
            __float2bfloat16((v).x - __bfloat162float(hx)),                    \
            __float2bfloat16((v).y - __bfloat162float(hy)));                   \
        *reinterpret_cast<__nv_bfloat162*>(pl + 2) = __halves2bfloat162(       \
            __float2bfloat16((v).z - __bfloat162float(hz)),                    \
            __float2bfloat16((v).w - __bfloat162float(hw)));                   \
    }

#define STAGE(s)                                                               \
    {                                                                          \
        _Pragma("unroll")                                                      \
        for (int i = 0; i < 4; i++) CVT_ST(AHI(s), ALO(s), arow + i * 32, ar[i]); \
        _Pragma("unroll")                                                      \
        for (int i = 0; i < 2; i++) CVT_ST(BHI(s), BLO(s), arow + i * 32, br[i]); \
    }

#define MAINLOOP()                                                             \
    LOAD_REGS(0);                                                              \
    STAGE(0);                                                                  \
    __syncthreads();                                                           \
    for (int t = 0; t < nt; t++) {                                             \
        const int pp = t & 1;                                                  \
        if (t + 1 < nt) LOAD_REGS((t + 1) * BKt);                              \
        _Pragma("unroll")                                                      \
        for (int kk = 0; kk < BKt; kk += 16) {                                 \
            wmma::fragment<wmma::matrix_a, 16, 16, 16, __nv_bfloat16, wmma::row_major> ah[2], al[2]; \
            wmma::fragment<wmma::matrix_b, 16, 16, 16, __nv_bfloat16, wmma::col_major> bh[2], bl[2]; \
            _Pragma("unroll")                                                  \
            for (int i = 0; i < 2; i++) {                                      \
                const __nv_bfloat16* pa = AHI(pp) + (wm * 32 + i * 16) * PADt + kk; \
                wmma::load_matrix_sync(ah[i], pa, PADt);                       \
                wmma::load_matrix_sync(al[i], pa + BMt * PADt, PADt);          \
            }                                                                  \
            _Pragma("unroll")                                                  \
            for (int j = 0; j < 2; j++) {                                      \
                const __nv_bfloat16* pb = BHI(pp) + (wn * 32 + j * 16) * PADt + kk; \
                wmma::load_matrix_sync(bh[j], pb, PADt);                       \
                wmma::load_matrix_sync(bl[j], pb + BNt * PADt, PADt);          \
            }                                                                  \
            _Pragma("unroll")                                                  \
            for (int i = 0; i < 2; i++)                                        \
                _Pragma("unroll")                                              \
                for (int j = 0; j < 2; j++) {                                  \
                    wmma::mma_sync(acc[i][j], ah[i], bh[j], acc[i][j]);        \
                    wmma::mma_sync(acc[i][j], ah[i], bl[j], acc[i][j]);        \
                    wmma::mma_sync(acc[i][j], al[i], bh[j], acc[i][j]);        \
                }                                                              \
        }                                                                      \
        if (t + 1 < nt) STAGE(1 - pp);                                         \
        __syncthreads();                                                       \
    }

#define PATCH_STORE()                                                          \
    {                                                                          \
        _Pragma("unroll")                                                      \
        for (int i = 0; i < 2; i++)                                            \
            _Pragma("unroll")                                                  \
            for (int j = 0; j < 2; j++)                                        \
                wmma::store_matrix_sync(patch + i * 16 * 32 + j * 16,          \
                                        acc[i][j], 32, wmma::mem_row_major);   \
        __syncwarp();                                                          \
    }

// ================= main GEMM =================
// modes: 0=C ; 1=maxpool into mp ; 2=C+mu/lv ; 3=C+plv ; 4=dmu/dlv/z2 (no C)
__global__ __launch_bounds__(256) void k_wgemm(
    const float* __restrict__ Ap, int lda,
    const float* __restrict__ Wp, int K,
    const float* __restrict__ bias,
    float* __restrict__ C, int N, int act, int mode,
    unsigned int* __restrict__ mp,
    float* __restrict__ aux0, float* __restrict__ aux1,
    const float* __restrict__ paux, float* __restrict__ z2out)
{
    const int ldw = K;
    extern __shared__ char smem[];

    const int tid = threadIdx.x, wid = tid >> 5, lid = tid & 31;
    const int bm = blockIdx.y * BMt, bn = blockIdx.x * BNt;
    const int wm = wid & 3, wn = wid >> 2;     // 4 x 2 warps, 32x32 each
    const int arow = tid >> 3, ak4 = tid & 7;

    float4 ar[4], br[2];
    wmma::fragment<wmma::accumulator, 16, 16, 16, float> acc[2][2];
#pragma unroll
    for (int i = 0; i < 2; i++)
#pragma unroll
        for (int j = 0; j < 2; j++)
            wmma::fill_fragment(acc[i][j], 0.0f);

    const int nt = K / BKt;
    MAINLOOP();

    float* patch = reinterpret_cast<float*>(smem) + wid * 1024;
    PATCH_STORE();

    const int cbase = bn + wn * 32;
    const int c0 = (lid & 7) * 4;

    if (mode == 1) {
        float mx[4] = {-CUDART_INF_F, -CUDART_INF_F, -CUDART_INF_F, -CUDART_INF_F};
#pragma unroll
        for (int it = 0; it < 8; it++) {
            int r = it * 4 + (lid >> 3);
#pragma unroll
            for (int j = 0; j < 4; j++) {
                float rr = patch[r * 32 + c0 + j] + __ldg(&bias[cbase + c0 + j]);
                rr = rr > 0.f ? rr : 0.2f * rr;
                mx[j] = fmaxf(mx[j], rr);
            }
        }
        int b = (bm + wm * 32) >> 6;
#pragma unroll
        for (int j = 0; j < 4; j++)
            atomicMax(&mp[b * N + cbase + c0 + j], f32_ordered(mx[j]));
        return;
    }

#pragma unroll
    for (int it = 0; it < 8; it++) {
        int r = it * 4 + (lid >> 3);
        int m = bm + wm * 32 + r;
        int n = cbase + c0;
        float4 v;
        float* vp = reinterpret_cast<float*>(&v);
#pragma unroll
        for (int j = 0; j < 4; j++) {
            float rr = patch[r * 32 + c0 + j] + __ldg(&bias[n + j]);
            if (act) rr = rr > 0.f ? rr : 0.2f * rr;
            vp[j] = rr;
        }
        if (mode != 4)
            *reinterpret_cast<float4*>(&C[(size_t)m * N + n]) = v;
        if (mode == 2) {
            if (n < 256)
                *reinterpret_cast<float4*>(&aux0[m * 256 + n]) = v;
            else
                *reinterpret_cast<float4*>(&aux1[m * 256 + n - 256]) = v;
        } else if (mode == 3) {
            if (n >= 768)
                *reinterpret_cast<float4*>(&aux0[m * 768 + n - 768]) = v;
        } else if (mode == 4) {
            if (n < 768) {
                *reinterpret_cast<float4*>(&aux0[m * 768 + n]) = v;
                float4 pv = *reinterpret_cast<const float4*>(&paux[(size_t)m * 1536 + n]);
                float4 z;
                z.x = v.x + pv.x; z.y = v.y + pv.y;
                z.z = v.z + pv.z; z.w = v.w + pv.w;
                *reinterpret_cast<float4*>(&z2out[m * 768 + n]) = z;
            } else {
                *reinterpret_cast<float4*>(&aux1[m * 768 + n - 768]) = v;
            }
        }
    }
}

// ================= tensorized dist + argmin =================
// grid (1024/64, 512/128, 64), block 256
__global__ __launch_bounds__(256) void k_distw(
    const float* __restrict__ recon,
    const float* __restrict__ book,
    const float* __restrict__ xr2,
    const float* __restrict__ book2,
    float* __restrict__ dist,
    unsigned long long* __restrict__ keys)
{
    extern __shared__ char smem[];

    const int tid = threadIdx.x, wid = tid >> 5, lid = tid & 31;
    const int c = blockIdx.z;
    const int bm = blockIdx.y * BMt, bn = blockIdx.x * BNt;
    const int wm = wid & 3, wn = wid >> 2;
    const int arow = tid >> 3, ak4 = tid & 7;

    const float* Ap = recon + c * 64;            // lda 4096
    const float* Wp = book + (size_t)c * 65536;  // ldw 64
    const int lda = 4096, ldw = 64;

    float4 ar[4], br[2];
    wmma::fragment<wmma::accumulator, 16, 16, 16, float> acc[2][2];
#pragma unroll
    for (int i = 0; i < 2; i++)
#pragma unroll
        for (int j = 0; j < 2; j++)
            wmma::fill_fragment(acc[i][j], 0.0f);

    const int nt = 2;    // K = 64
    MAINLOOP();

    float* patch = reinterpret_cast<float*>(smem) + wid * 1024;
    PATCH_STORE();

    const int sbase = bn + wn * 32;
    const int c0 = (lid & 7) * 4;

#pragma unroll
    for (int it = 0; it < 8; it++) {
        int r = it * 4 + (lid >> 3);
        int m = bm + wm * 32 + r;
        int s = sbase + c0;
        float x2 = __ldg(&xr2[m * 64 + c]);
        float4 v;
        float* vp = reinterpret_cast<float*>(&v);
        unsigned long long kbest = ~0ull;
#pragma unroll
        for (int j = 0; j < 4; j++) {
            float dval = x2 + __ldg(&book2[c * 1024 + s + j])
                       - 2.0f * patch[r * 32 + c0 + j];
            vp[j] = dval;
            unsigned long long key =
                ((unsigned long long)f32_ordered(dval) << 32) | (unsigned int)(s + j);
            kbest = min(kbest, key);
        }
        *reinterpret_cast<float4*>(&dist[((size_t)m * 64 + c) * 1024 + s]) = v;
#pragma unroll
        for (int off = 4; off; off >>= 1) {
            unsigned long long o = __shfl_xor_sync(0xffffffffu, kbest, off, 8);
            kbest = min(kbest, o);
        }
        if ((lid & 7) == 0) atomicMin(&keys[m * 64 + c], kbest);
    }
}

// ================= fused init: hmaxu, keys, book2 rowsq =================
__global__ void k_init(unsigned int* __restrict__ hmaxu,
                       unsigned long long* __restrict__ keys,
                       const float* __restrict__ book,
                       float* __restrict__ book2)
{
    int idx = blockIdx.x * blockDim.x + threadIdx.x;
    if (idx < 512 * 512) hmaxu[idx] = f32_ordered(-CUDART_INF_F);
    if (idx < 512 * 64)  keys[idx] = ~0ull;
    if (idx < 64 * 1024) {
        const float4* p = reinterpret_cast<const float4*>(book + (size_t)idx * 64);
        float s = 0.f;
#pragma unroll
        for (int i = 0; i < 16; i++) {
            float4 v = p[i];
            s += v.x * v.x + v.y * v.y + v.z * v.z + v.w * v.w;
        }
        book2[idx] = s;
    }
}

__global__ void k_cvthmax(const unsigned int* __restrict__ hmaxu, float* __restrict__ hmax)
{
    int idx = blockIdx.x * blockDim.x + threadIdx.x;
    if (idx < 512 * 512) hmax[idx] = f32_unordered(hmaxu[idx]);
}

__global__ void k_cat(const float* __restrict__ z1, const float* __restrict__ h,
                      float* __restrict__ dst)
{
    int idx = blockIdx.x * blockDim.x + threadIdx.x;
    if (idx >= 512 * 2304) return;
    int b = idx / 2304, j = idx - b * 2304;
    dst[idx] = (j < 256) ? z1[(size_t)b * 512 + j] : h[(size_t)b * 2048 + (j - 256)];
}

__global__ void k_rowsq(const float* __restrict__ src, float* __restrict__ dst, int nrows)
{
    int idx = blockIdx.x * blockDim.x + threadIdx.x;
    if (idx >= nrows) return;
    const float4* p = reinterpret_cast<const float4*>(src + (size_t)idx * 64);
    float s = 0.f;
#pragma unroll
    for (int i = 0; i < 16; i++) {
        float4 v = p[i];
        s += v.x * v.x + v.y * v.y + v.z * v.z + v.w * v.w;
    }
    dst[idx] = s;
}

__global__ void k_writeidx(const unsigned long long* __restrict__ keys,
                           float* __restrict__ out)
{
    int idx = blockIdx.x * blockDim.x + threadIdx.x;
    if (idx < 512 * 64)
        out[idx] = (float)(unsigned int)(keys[idx] & 0xFFFFFFFFull);
}

// ================= launcher =================
#define GEMM_SMEM 61440

extern "C" void kernel_launch(void* const* d_in, const int* in_sizes, int n_in,
                              void* d_out, int out_size)
{
    const float* x        = (const float*)d_in[0];
    const float* codebook = (const float*)d_in[1];
    const float* enc_w1   = (const float*)d_in[2];
    const float* enc_b1   = (const float*)d_in[3];
    const float* enc_w2   = (const float*)d_in[4];
    const float* enc_b2   = (const float*)d_in[5];
    const float* inf1_w   = (const float*)d_in[6];
    const float* inf1_b   = (const float*)d_in[7];
    const float* inf2_w1  = (const float*)d_in[8];
    const float* inf2_b1  = (const float*)d_in[9];
    const float* inf2_w2  = (const float*)d_in[10];
    const float* inf2_b2  = (const float*)d_in[11];
    const float* prior_w1 = (const float*)d_in[12];
    const float* prior_b1 = (const float*)d_in[13];
    const float* prior_w2 = (const float*)d_in[14];
    const float* prior_b2 = (const float*)d_in[15];
    const float* dec_w1   = (const float*)d_in[16];
    const float* dec_b1   = (const float*)d_in[17];
    const float* dec_w2   = (const float*)d_in[18];
    const float* dec_b2   = (const float*)d_in[19];
    float* out = (float*)d_out;

    float *hmax, *h2, *h3, *t, *p, *cat, *z2, *xr2, *book2;
    unsigned int* hmaxu;
    unsigned long long* keys;
    cudaGetSymbolAddress((void**)&hmaxu, g_hmaxu);
    cudaGetSymbolAddress((void**)&hmax,  g_hmax);
    cudaGetSymbolAddress((void**)&h2,    g_h2);
    cudaGetSymbolAddress((void**)&h3,    g_h3);
    cudaGetSymbolAddress((void**)&t,     g_t);
    cudaGetSymbolAddress((void**)&p,     g_p);
    cudaGetSymbolAddress((void**)&cat,   g_cat);
    cudaGetSymbolAddress((void**)&z2,    g_z2);
    cudaGetSymbolAddress((void**)&xr2,   g_xr2);
    cudaGetSymbolAddress((void**)&book2, g_book2);
    cudaGetSymbolAddress((void**)&keys,  g_keys);

    cudaFuncSetAttribute(k_wgemm, cudaFuncAttributeMaxDynamicSharedMemorySize, GEMM_SMEM);
    cudaFuncSetAttribute(k_distw, cudaFuncAttributeMaxDynamicSharedMemorySize, GEMM_SMEM);

    // 0) fused init (hmaxu, keys, book2)
    k_init<<<(512*512+255)/256, 256>>>(hmaxu, keys, codebook, book2);
    // 1) enc1 + fused maxpool
    k_wgemm<<<dim3(512/64, 32768/128), 256, GEMM_SMEM>>>(
        x, 64, enc_w1, 64, enc_b1, nullptr, 512, 1, 1, hmaxu, nullptr, nullptr, nullptr, nullptr);
    k_cvthmax<<<(512*512+255)/256, 256>>>(hmaxu, hmax);
    // 2) enc2
    k_wgemm<<<dim3(2048/64, 4), 256, GEMM_SMEM>>>(
        hmax, 512, enc_w2, 512, enc_b2, h2, 2048, 0, 0, nullptr, nullptr, nullptr, nullptr, nullptr);
    // 3) inf1 (+ mu/lv)
    k_wgemm<<<dim3(512/64, 4), 256, GEMM_SMEM>>>(
        h2, 2048, inf1_w, 2048, inf1_b, h3, 512, 0, 2, nullptr,
        out + OFF_MU, out + OFF_LV, nullptr, nullptr);
    // 4) prior
    k_wgemm<<<dim3(2048/64, 4), 256, GEMM_SMEM>>>(
        h3, 512, prior_w1, 256, prior_b1, t, 2048, 1, 0, nullptr, nullptr, nullptr, nullptr, nullptr);
    k_wgemm<<<dim3(1536/64, 4), 256, GEMM_SMEM>>>(
        t, 2048, prior_w2, 2048, prior_b2, p, 1536, 0, 3, nullptr,
        out + OFF_PLV, nullptr, nullptr, nullptr);
    // 5) inf2
    k_cat<<<(512*2304+255)/256, 256>>>(h3, h2, cat);
    k_wgemm<<<dim3(2048/64, 4), 256, GEMM_SMEM>>>(
        cat, 2304, inf2_w1, 2304, inf2_b1, t, 2048, 1, 0, nullptr, nullptr, nullptr, nullptr, nullptr);
    k_wgemm<<<dim3(1536/64, 4), 256, GEMM_SMEM>>>(
        t, 2048, inf2_w2, 2048, inf2_b2, nullptr, 1536, 0, 4, nullptr,
        out + OFF_DMU, out + OFF_DLV, p, z2);
    // 6) decoder
    k_wgemm<<<dim3(2048/64, 4), 256, GEMM_SMEM>>>(
        z2, 768, dec_w1, 768, dec_b1, t, 2048, 1, 0, nullptr, nullptr, nullptr, nullptr, nullptr);
    k_wgemm<<<dim3(4096/64, 4), 256, GEMM_SMEM>>>(
        t, 2048, dec_w2, 2048, dec_b2, out + OFF_RECON, 4096, 0, 0, nullptr, nullptr, nullptr, nullptr, nullptr);
    // 7) dist + argmin
    k_rowsq<<<(512*64+255)/256, 256>>>(out + OFF_RECON, xr2, 512*64);
    k_distw<<<dim3(1024/64, 512/128, 64), 256, GEMM_SMEM>>>(
        out + OFF_RECON, codebook, xr2, book2, out + OFF_DIST, keys);
    k_writeidx<<<(512*64+255)/256, 256>>>(keys, out + OFF_IDX);
}